// round 14
// baseline (speedup 1.0000x reference)
#include <cuda_runtime.h>
#include <cuda_bf16.h>
#include <cuda_fp16.h>
#include <math.h>
#include <stdint.h>

#define K_CODES 1024
#define D_DIM   256
#define N_ROWS  131072

#define FLAG_THRESH  3.5f      // mixed bf16-MMA + fp16-HFMA2 gap-err ~6 sigma
#define RESCUE_RPB   8

// ---------------- scratch (device globals; no allocations allowed) ----------
__device__ float        d_cnorm[K_CODES];
__device__ float        d_embedT[K_CODES * D_DIM];
__device__ uint32_t     d_eBfrag[32 * 2048];     // bf16 MMA frags, dims 0..127
__device__ uint32_t     d_eBf16[8 * 8192];       // fp16 h2 frags, dims 128..255
__device__ unsigned int d_counts[K_CODES];
__device__ float        d_loss_partial[1024];
__device__ int          d_nflag;
__device__ int          d_flaglist[N_ROWS];

__device__ __forceinline__ uint32_t pack_bf2(float a, float b) {
    __nv_bfloat16 ha = __float2bfloat16_rn(a), hb = __float2bfloat16_rn(b);
    return (uint32_t)__bfloat16_as_ushort(ha) |
           ((uint32_t)__bfloat16_as_ushort(hb) << 16);
}
__device__ __forceinline__ uint32_t pack_h2(float a, float b) {
    __half2 h = __floats2half2_rn(a, b);
    return *(uint32_t*)&h;
}

// ---------------------------------------------------------------------------
// Prep 1: emulated codebook norms, fp32 transpose
// ---------------------------------------------------------------------------
__global__ void vq_prep(const float* __restrict__ embed) {
    int k = blockIdx.x * blockDim.x + threadIdx.x;
    float s = 0.0f;
    for (int d = 0; d < D_DIM; ++d) {
        float v = embed[(size_t)d * K_CODES + k];
        s = __fadd_rn(s, __fmul_rn(v, v));
        d_embedT[(size_t)k * D_DIM + d] = v;
    }
    d_cnorm[k]  = s;
    d_counts[k] = 0u;
    if (k == 0) d_nflag = 0;
}

// ---------------------------------------------------------------------------
// Prep 2: bf16 MMA B fragments for dims 0..127 (chunk-linear, g = kc*4+dc)
// ---------------------------------------------------------------------------
__global__ void vq_prep_frag(const float* __restrict__ embed) {
    const int g = blockIdx.x;          // 0..31
    const int kc = g >> 2, dc = g & 3;
    #pragma unroll
    for (int q = 0; q < 4; ++q) {
        int e    = q * 256 + threadIdx.x;   // 0..1023
        int ks   = e >> 9;
        int nt   = (e >> 5) & 15;
        int lane = e & 31;
        int t4   = lane & 3;
        int gq   = lane >> 2;
        int code = kc * 128 + nt * 8 + gq;
        int db   = dc * 32 + ks * 16;
        float e0 = embed[(size_t)(db + 2*t4)     * K_CODES + code];
        float e1 = embed[(size_t)(db + 2*t4 + 1) * K_CODES + code];
        float e2 = embed[(size_t)(db + 2*t4 + 8) * K_CODES + code];
        float e3 = embed[(size_t)(db + 2*t4 + 9) * K_CODES + code];
        size_t o = (size_t)g * 2048 + (size_t)e * 2;
        d_eBfrag[o]     = pack_bf2(e0, e1);
        d_eBfrag[o + 1] = pack_bf2(e2, e3);
    }
}

// ---------------------------------------------------------------------------
// Prep 3: fp16 half2 B fragments for dims 128..255
//   d_eBf16[kc*8192 + d*64 + tg*16 + nt] = h2(E[128+d][c], E[128+d][c+1]),
//   c = kc*128 + nt*8 + tg*2
// ---------------------------------------------------------------------------
__global__ void vq_prep_frag16(const float* __restrict__ embed) {
    #pragma unroll
    for (int q = 0; q < 4; ++q) {
        int e   = blockIdx.x * 1024 + q * 256 + threadIdx.x;  // 0..65535
        int kc  = e >> 13;
        int rem = e & 8191;
        int d   = rem >> 6;
        int idx = rem & 63;
        int tg  = idx >> 4;
        int nt  = idx & 15;
        int c   = kc * 128 + nt * 8 + tg * 2;
        float v0 = embed[(size_t)(128 + d) * K_CODES + c];
        float v1 = embed[(size_t)(128 + d) * K_CODES + c + 1];
        d_eBf16[e] = pack_h2(v0, v1);
    }
}

// ncu steering dummies (so -s 5 lands on vq_main)
__global__ void vq_dummy() {}

// ---------------------------------------------------------------------------
// SMEM (bytes):
//   [0,4096)        sCn (1024 f32)
//   [4096,4608)     sIdx (128 int)
//   [4608,4672)     sRed
//   [4672,37440)    fragA  (8 mt x 8 ks16 x 128 u32, bf16x2 dims 0..127)
//   [37440,45632)   fragB  (2048 u32, single buffer)
//   [45632,78912)   sAf    (128 rows x 130 half, dims 128..255)
//   [78912,111680)  sBf    (128 d x 64 h2, per-kc)
// 111,680 B/CTA -> 2 CTAs/SM
// ---------------------------------------------------------------------------
#define SM_CN   0
#define SM_IDX  4096
#define SM_RED  4608
#define SM_A    4672
#define SM_B    37440
#define SM_AF   45632
#define SM_BF   78912
#define SMEM_TOTAL 111680

__device__ __forceinline__ void mma_bf16(float c[4], uint32_t a0, uint32_t a1,
                                         uint32_t a2, uint32_t a3,
                                         uint32_t b0, uint32_t b1) {
    asm volatile(
        "mma.sync.aligned.m16n8k16.row.col.f32.bf16.bf16.f32 "
        "{%0,%1,%2,%3}, {%4,%5,%6,%7}, {%8,%9}, {%0,%1,%2,%3};"
        : "+f"(c[0]), "+f"(c[1]), "+f"(c[2]), "+f"(c[3])
        : "r"(a0), "r"(a1), "r"(a2), "r"(a3), "r"(b0), "r"(b1));
}

__device__ __forceinline__ void top2_upd(float& v1, float& v2, int& i1,
                                         float d, int code) {
    if (d < v1)      { v2 = v1; v1 = d; i1 = code; }
    else if (d < v2) { v2 = d; }
}

__global__ void __launch_bounds__(256, 2)
vq_main_mma(const float* __restrict__ inputs, float* __restrict__ out) {
    extern __shared__ char smem[];
    float*    sCn   = (float*)(smem + SM_CN);
    int*      sIdx  = (int*)(smem + SM_IDX);
    float*    sRed  = (float*)(smem + SM_RED);
    uint32_t* fragA = (uint32_t*)(smem + SM_A);
    uint32_t* fragB = (uint32_t*)(smem + SM_B);
    __half*   sAfH  = (__half*)(smem + SM_AF);
    uint32_t* sBf   = (uint32_t*)(smem + SM_BF);

    const int t    = threadIdx.x;
    const int wid  = t >> 5;
    const int lane = t & 31;
    const int tg   = lane & 3;
    const int row0 = blockIdx.x * 128;
    const int rA   = wid * 16 + (lane >> 2);

    for (int i = t; i < K_CODES; i += 256) sCn[i] = d_cnorm[i];

    // ---- Stage A: dims 0..127 -> bf16 fragA; dims 128..255 -> sAf fp16 ----
    {
        const float4* in4 = (const float4*)(inputs + (size_t)row0 * D_DIM);
        #pragma unroll
        for (int i = 0; i < 32; ++i) {
            int l   = i * 256 + t;           // 0..8191
            int row = l >> 6;
            int d4  = l & 63;
            float4 v = in4[row * 64 + d4];
            if (d4 < 32) {
                int d   = d4 * 4;
                int mt  = row >> 4, r16 = row & 15;
                int ks16 = d >> 4;           // 0..7
                int o    = d & 15;
                int reg  = ((o & 8) ? 2 : 0) + ((r16 >= 8) ? 1 : 0);
                int t0   = (o & 7) >> 1;
                uint32_t* p = fragA + ((mt * 8 + ks16) * 32 + (r16 & 7) * 4 + t0) * 4 + reg;
                p[0] = pack_bf2(v.x, v.y);
                p[4] = pack_bf2(v.z, v.w);
            } else {
                int dl = (d4 - 32) * 4;      // local dim 0..127 (global 128+)
                uint32_t* p = (uint32_t*)(sAfH + row * 130 + dl);
                p[0] = pack_h2(v.x, v.y);
                p[1] = pack_h2(v.z, v.w);
            }
        }
    }
    // ---- Stage fragB chunk 0 ----
    {
        const uint4* src = (const uint4*)d_eBfrag;
        uint4* dst = (uint4*)fragB;
        dst[t]       = src[t];
        dst[t + 256] = src[t + 256];
    }
    __syncthreads();

    float acc[16][4];
    #pragma unroll
    for (int nt = 0; nt < 16; ++nt)
        #pragma unroll
        for (int r = 0; r < 4; ++r) acc[nt][r] = 0.0f;

    const __half2 hz = __floats2half2_rn(0.0f, 0.0f);
    __half2 facc0[16], facc1[16];
    #pragma unroll
    for (int nt = 0; nt < 16; ++nt) { facc0[nt] = hz; facc1[nt] = hz; }

    float v1a = 3.4e38f, v2a = 3.4e38f; int i1a = 0;   // row rA
    float v1b = 3.4e38f, v2b = 3.4e38f; int i1b = 0;   // row rA+8

    const uint32_t* fA = fragA + wid * 1024 + lane * 4;

    for (int g = 0; g < 32; ++g) {          // g = kc*4 + dc
        const int dc = g & 3;

        // stage sBf for this kc at kc start (dims 128..255 fp16 frags)
        if (dc == 0) {
            const uint4* src = (const uint4*)(d_eBf16 + (size_t)(g >> 2) * 8192);
            uint4* dst = (uint4*)sBf;
            #pragma unroll
            for (int q = 0; q < 8; ++q)
                dst[q * 256 + t] = src[q * 256 + t];
            __syncthreads();
        }

        // prefetch next fragB chunk into regs
        uint4 pv0, pv1;
        if (g < 31) {
            const uint4* src = (const uint4*)(d_eBfrag + (size_t)(g + 1) * 2048);
            pv0 = src[t];
            pv1 = src[t + 256];
        }

        // ---- MMA: 2 k16-steps x 16 nt (dims dc*32..dc*32+31) ----
        {
            const uint32_t* fB = fragB + lane * 2;
            #pragma unroll
            for (int ks = 0; ks < 2; ++ks) {
                int ks16 = dc * 2 + ks;
                uint4 a = *(const uint4*)(fA + ks16 * 128);
                #pragma unroll
                for (int nt = 0; nt < 16; ++nt) {
                    uint2 b = *(const uint2*)(fB + (ks * 16 + nt) * 64);
                    mma_bf16(acc[nt], a.x, a.y, a.z, a.w, b.x, b.y);
                }
            }
        }

        // ---- HFMA2: dims 128+dc*32 .. +31 for this kc's 128 codes ----
        {
            const int d0 = dc * 32;
            #pragma unroll 4
            for (int dd = 0; dd < 32; ++dd) {
                int d = d0 + dd;
                __half2 a0s = __half2half2(sAfH[rA * 130 + d]);
                __half2 a1s = __half2half2(sAfH[(rA + 8) * 130 + d]);
                const uint4* bp = (const uint4*)(sBf + d * 64 + tg * 16);
                uint4 b0 = bp[0], b1 = bp[1], b2 = bp[2], b3 = bp[3];
                const __half2* bh0 = (const __half2*)&b0;
                const __half2* bh1 = (const __half2*)&b1;
                const __half2* bh2 = (const __half2*)&b2;
                const __half2* bh3 = (const __half2*)&b3;
                #pragma unroll
                for (int j = 0; j < 4; ++j) {
                    facc0[j]      = __hfma2(a0s, bh0[j], facc0[j]);
                    facc1[j]      = __hfma2(a1s, bh0[j], facc1[j]);
                    facc0[4 + j]  = __hfma2(a0s, bh1[j], facc0[4 + j]);
                    facc1[4 + j]  = __hfma2(a1s, bh1[j], facc1[4 + j]);
                    facc0[8 + j]  = __hfma2(a0s, bh2[j], facc0[8 + j]);
                    facc1[8 + j]  = __hfma2(a1s, bh2[j], facc1[8 + j]);
                    facc0[12 + j] = __hfma2(a0s, bh3[j], facc0[12 + j]);
                    facc1[12 + j] = __hfma2(a1s, bh3[j], facc1[12 + j]);
                }
            }
        }

        // ---- kc epilogue: merge facc, dist, top-2 ----
        if (dc == 3) {
            int kc = g >> 2;
            #pragma unroll
            for (int nt = 0; nt < 16; ++nt) {
                float2 f0 = __half22float2(facc0[nt]);
                float2 f1 = __half22float2(facc1[nt]);
                int code = kc * 128 + nt * 8 + tg * 2;
                float c0 = sCn[code]     - 2.0f * (acc[nt][0] + f0.x);
                float c1 = sCn[code + 1] - 2.0f * (acc[nt][1] + f0.y);
                float c2 = sCn[code]     - 2.0f * (acc[nt][2] + f1.x);
                float c3 = sCn[code + 1] - 2.0f * (acc[nt][3] + f1.y);
                top2_upd(v1a, v2a, i1a, c0, code);
                top2_upd(v1a, v2a, i1a, c1, code + 1);
                top2_upd(v1b, v2b, i1b, c2, code);
                top2_upd(v1b, v2b, i1b, c3, code + 1);
                acc[nt][0] = acc[nt][1] = acc[nt][2] = acc[nt][3] = 0.0f;
                facc0[nt] = hz; facc1[nt] = hz;
            }
        }

        __syncthreads();     // all reads of fragB done
        if (g < 31) {
            uint4* dst = (uint4*)fragB;
            dst[t]       = pv0;
            dst[t + 256] = pv1;
        }
        __syncthreads();     // fragB (and, at kc start next iter, sBf) ready
    }

    // ---- merge top-2 across the 4 lanes sharing each row ----
    #pragma unroll
    for (int off = 1; off < 4; off <<= 1) {
        float w1 = __shfl_down_sync(0xffffffffu, v1a, off, 4);
        int   wi = __shfl_down_sync(0xffffffffu, i1a, off, 4);
        float w2 = __shfl_down_sync(0xffffffffu, v2a, off, 4);
        if (w1 < v1a || (w1 == v1a && wi < i1a)) {
            v2a = fminf(v1a, w2); v1a = w1; i1a = wi;
        } else v2a = fminf(v2a, w1);
        w1 = __shfl_down_sync(0xffffffffu, v1b, off, 4);
        wi = __shfl_down_sync(0xffffffffu, i1b, off, 4);
        w2 = __shfl_down_sync(0xffffffffu, v2b, off, 4);
        if (w1 < v1b || (w1 == v1b && wi < i1b)) {
            v2b = fminf(v1b, w2); v1b = w1; i1b = wi;
        } else v2b = fminf(v2b, w1);
    }

    const size_t ND = (size_t)N_ROWS * D_DIM;
    if ((lane & 3) == 0) {
        int rB = rA + 8;
        sIdx[rA] = i1a;
        sIdx[rB] = i1b;
        if (v2a - v1a < FLAG_THRESH) {
            int pos = atomicAdd(&d_nflag, 1);
            d_flaglist[pos] = row0 + rA;
        }
        if (v2b - v1b < FLAG_THRESH) {
            int pos = atomicAdd(&d_nflag, 1);
            d_flaglist[pos] = row0 + rB;
        }
        atomicAdd(&d_counts[i1a], 1u);
        atomicAdd(&d_counts[i1b], 1u);
        out[ND + 2 + (size_t)(row0 + rA)] = (float)i1a;
        out[ND + 2 + (size_t)(row0 + rB)] = (float)i1b;
    }
    __syncthreads();

    // ---- quantize (= q exactly) + loss partials ----
    float lsum = 0.0f;
    const float4* inp4 = (const float4*)(inputs + (size_t)row0 * D_DIM);
    float4*       out4 = (float4*)(out + (size_t)row0 * D_DIM);
    const float4* eT4  = (const float4*)d_embedT;
    #pragma unroll 4
    for (int it = 0; it < 32; ++it) {
        int l  = it * 256 + t;
        int r  = l >> 6;
        int d4 = l & 63;
        float4 x = inp4[r * 64 + d4];
        int    k = sIdx[r];
        float4 q = eT4[(size_t)k * 64 + d4];
        float dx = q.x - x.x, dy = q.y - x.y, dz = q.z - x.z, dw = q.w - x.w;
        lsum += dx * dx + dy * dy + dz * dz + dw * dw;
        out4[r * 64 + d4] = q;
    }
    #pragma unroll
    for (int off = 16; off; off >>= 1)
        lsum += __shfl_down_sync(0xffffffffu, lsum, off);
    if ((t & 31) == 0) sRed[t >> 5] = lsum;
    __syncthreads();
    if (t == 0) {
        float s = 0.0f;
        #pragma unroll
        for (int w = 0; w < 8; ++w) s += sRed[w];
        d_loss_partial[blockIdx.x] = s;
    }
}

// ---------------------------------------------------------------------------
// Rescue: re-decide flagged rows with reference-emulated fp32 arithmetic
// ---------------------------------------------------------------------------
__global__ void __launch_bounds__(256)
vq_fix(const float* __restrict__ inputs, float* __restrict__ out) {
    __shared__ float sx[RESCUE_RPB][D_DIM];
    __shared__ float sdist[RESCUE_RPB][K_CODES];
    __shared__ float ssx2[RESCUE_RPB];
    __shared__ int   srow[RESCUE_RPB];
    __shared__ int   sbest[RESCUE_RPB];
    const int t = threadIdx.x;
    const size_t ND = (size_t)N_ROWS * D_DIM;

    const int nf = d_nflag;
    for (int base = blockIdx.x * RESCUE_RPB; base < nf;
         base += gridDim.x * RESCUE_RPB) {
        const int cnt = min(RESCUE_RPB, nf - base);
        __syncthreads();
        if (t < cnt) srow[t] = d_flaglist[base + t];
        __syncthreads();
        for (int r = 0; r < cnt; ++r)
            sx[r][t] = inputs[(size_t)srow[r] * D_DIM + t];
        __syncthreads();
        if (t < cnt) {
            float s = 0.0f;
            for (int d = 0; d < D_DIM; ++d)
                s = __fadd_rn(s, __fmul_rn(sx[t][d], sx[t][d]));
            ssx2[t] = s;
        }
        __syncthreads();

        #pragma unroll
        for (int c = 0; c < 4; ++c) {
            const int k = c * 256 + t;
            const float* e = d_embedT + (size_t)k * D_DIM;
            float acc[RESCUE_RPB];
            #pragma unroll
            for (int r = 0; r < RESCUE_RPB; ++r) acc[r] = 0.0f;
            for (int d = 0; d < D_DIM; ++d) {
                float ev = e[d];
                #pragma unroll
                for (int r = 0; r < RESCUE_RPB; ++r)
                    acc[r] = __fmaf_rn(sx[r][d], ev, acc[r]);
            }
            #pragma unroll
            for (int r = 0; r < RESCUE_RPB; ++r) {
                float twod = __fadd_rn(acc[r], acc[r]);
                float t1   = __fsub_rn(ssx2[r], twod);
                sdist[r][k] = __fadd_rn(t1, d_cnorm[k]);
            }
        }
        __syncthreads();

        if (t < cnt) {
            float best = 3.4e38f; int bk = 0;
            for (int k = 0; k < K_CODES; ++k) {
                float v = sdist[t][k];
                if (v < best) { best = v; bk = k; }
            }
            sbest[t] = bk;
            int oldk = (int)out[ND + 2 + (size_t)srow[t]];
            if (oldk != bk) {
                atomicAdd(&d_counts[bk], 1u);
                atomicAdd(&d_counts[oldk], 0xFFFFFFFFu);
                out[ND + 2 + (size_t)srow[t]] = (float)bk;
            }
        }
        __syncthreads();
        for (int r = 0; r < cnt; ++r)
            out[(size_t)srow[r] * D_DIM + t] =
                d_embedT[(size_t)sbest[r] * D_DIM + t];
    }
}

// ---------------------------------------------------------------------------
// Finalize: loss mean + perplexity
// ---------------------------------------------------------------------------
__global__ void vq_finalize(float* __restrict__ out) {
    __shared__ float sl[1024];
    __shared__ float se[1024];
    int t = threadIdx.x;
    sl[t] = d_loss_partial[t];
    float avg = (float)d_counts[t] * (1.0f / (float)N_ROWS);
    se[t] = avg * logf(avg + 1e-10f);
    __syncthreads();
    for (int s = 512; s; s >>= 1) {
        if (t < s) { sl[t] += sl[t + s]; se[t] += se[t + s]; }
        __syncthreads();
    }
    if (t == 0) {
        const size_t ND = (size_t)N_ROWS * D_DIM;
        out[ND]     = sl[0] / ((float)N_ROWS * (float)D_DIM);
        out[ND + 1] = expf(-se[0]);
    }
}

// ---------------------------------------------------------------------------
extern "C" void kernel_launch(void* const* d_in, const int* in_sizes, int n_in,
                              void* d_out, int out_size) {
    const float* inputs = (const float*)d_in[0];  // [131072, 256]
    const float* embed  = (const float*)d_in[1];  // [256, 1024]
    float* out = (float*)d_out;

    cudaFuncSetAttribute(vq_main_mma,
                         cudaFuncAttributeMaxDynamicSharedMemorySize,
                         SMEM_TOTAL);

    vq_prep<<<8, 128>>>(embed);          // launch 0
    vq_prep_frag<<<32, 256>>>(embed);    // launch 1
    vq_prep_frag16<<<64, 256>>>(embed);  // launch 2
    vq_dummy<<<1, 32>>>();               // launch 3
    vq_dummy<<<1, 32>>>();               // launch 4
    vq_main_mma<<<N_ROWS / 128, 256, SMEM_TOTAL>>>(inputs, out);  // launch 5 (ncu)
    vq_fix<<<256, 256>>>(inputs, out);
    vq_finalize<<<1, 1024>>>(out);
}

// round 15
// speedup vs baseline: 4.6846x; 4.6846x over previous
#include <cuda_runtime.h>
#include <cuda_bf16.h>
#include <math.h>
#include <stdint.h>

#define K_CODES 1024
#define D_DIM   256
#define N_ROWS  131072

#define FLAG_THRESH  0.65f     // bf16 dist-err std ~0.07 -> ~6.5 sigma on diff
#define RESCUE_RPB   8

// ---------------- scratch (device globals; no allocations allowed) ----------
__device__ float        d_cnorm[K_CODES];            // emulated sum(e*e)
__device__ float        d_embedT[K_CODES * D_DIM];   // fp32 codebook, k-major
__device__ uint32_t     d_eBfrag[64 * 2048];         // preformatted B fragments
__device__ unsigned int d_counts[K_CODES];
__device__ float        d_loss_partial[1024];
__device__ int          d_nflag;
__device__ int          d_flaglist[N_ROWS];

__device__ __forceinline__ uint32_t pack_bf2(float a, float b) {
    __nv_bfloat16 ha = __float2bfloat16_rn(a), hb = __float2bfloat16_rn(b);
    return (uint32_t)__bfloat16_as_ushort(ha) |
           ((uint32_t)__bfloat16_as_ushort(hb) << 16);
}

// ---------------------------------------------------------------------------
// Prep 1: emulated codebook norms (ascending-d, mul-then-add), fp32 transpose
// ---------------------------------------------------------------------------
__global__ void vq_prep(const float* __restrict__ embed) {
    int k = blockIdx.x * blockDim.x + threadIdx.x;  // 0..1023
    float s = 0.0f;
    for (int d = 0; d < D_DIM; ++d) {
        float v = embed[(size_t)d * K_CODES + k];
        s = __fadd_rn(s, __fmul_rn(v, v));
        d_embedT[(size_t)k * D_DIM + d] = v;
    }
    d_cnorm[k]  = s;
    d_counts[k] = 0u;
    if (k == 0) d_nflag = 0;
}

// ---------------------------------------------------------------------------
// Prep 2: bf16 B fragments for mma.m16n8k16 (chunk-linear, g = kc*8 + dc)
// ---------------------------------------------------------------------------
__global__ void vq_prep_frag(const float* __restrict__ embed) {
    const int g = blockIdx.x;          // 0..63
    const int kc = g >> 3, dc = g & 7;
    #pragma unroll
    for (int q = 0; q < 4; ++q) {
        int e    = q * 256 + threadIdx.x;   // 0..1023
        int ks   = e >> 9;
        int nt   = (e >> 5) & 15;
        int lane = e & 31;
        int t4   = lane & 3;
        int gq   = lane >> 2;
        int code = kc * 128 + nt * 8 + gq;
        int db   = dc * 32 + ks * 16;
        float e0 = embed[(size_t)(db + 2*t4)     * K_CODES + code];
        float e1 = embed[(size_t)(db + 2*t4 + 1) * K_CODES + code];
        float e2 = embed[(size_t)(db + 2*t4 + 8) * K_CODES + code];
        float e3 = embed[(size_t)(db + 2*t4 + 9) * K_CODES + code];
        uint32_t* dst = d_eBfrag + ((size_t)g * 2048) + (size_t)e * 2;
        dst[0] = pack_bf2(e0, e1);
        dst[1] = pack_bf2(e2, e3);
    }
}

// ---------------------------------------------------------------------------
// SMEM layout (bytes):
//   [0,4096)        sCn   (1024 f32)
//   [4096,4608)     sIdx  (128 int)
//   [4608,4640)     sRed  (8 f32)
//   [4640,70176)    fragA (8 mt x 16 kstep16 x 32 lanes x 4 regs, bf16x2)
//   [70176,102944)  fragB (2 bufs x 4096 u32 = 2 chunks per buffer)
// 102.9KB/CTA -> 2 CTAs/SM (206KB of 227KB)
// ---------------------------------------------------------------------------
#define SM_CN   0
#define SM_IDX  4096
#define SM_RED  4608
#define SM_A    4640
#define SM_B    70176
#define SMEM_TOTAL 102944
#define BSTRIDE 4096        // u32 per fragB buffer (= 2 chunks)

__device__ __forceinline__ void mma_bf16(float c[4], uint32_t a0, uint32_t a1,
                                         uint32_t a2, uint32_t a3,
                                         uint32_t b0, uint32_t b1) {
    asm volatile(
        "mma.sync.aligned.m16n8k16.row.col.f32.bf16.bf16.f32 "
        "{%0,%1,%2,%3}, {%4,%5,%6,%7}, {%8,%9}, {%0,%1,%2,%3};"
        : "+f"(c[0]), "+f"(c[1]), "+f"(c[2]), "+f"(c[3])
        : "r"(a0), "r"(a1), "r"(a2), "r"(a3), "r"(b0), "r"(b1));
}

__device__ __forceinline__ void top2_upd(float& v1, float& v2, int& i1,
                                         float d, int code) {
    if (d < v1)      { v2 = v1; v1 = d; i1 = code; }
    else if (d < v2) { v2 = d; }
}

__global__ void __launch_bounds__(256, 2)
vq_main_mma(const float* __restrict__ inputs, float* __restrict__ out) {
    extern __shared__ char smem[];
    float*    sCn   = (float*)(smem + SM_CN);
    int*      sIdx  = (int*)(smem + SM_IDX);
    float*    sRed  = (float*)(smem + SM_RED);
    uint32_t* fragA = (uint32_t*)(smem + SM_A);
    uint32_t* fragB = (uint32_t*)(smem + SM_B);

    const int t    = threadIdx.x;
    const int wid  = t >> 5;
    const int lane = t & 31;
    const int row0 = blockIdx.x * 128;

    for (int i = t; i < K_CODES; i += 256) sCn[i] = d_cnorm[i];

    // ---- Stage A (128 rows x 256 d) -> bf16 fragment-major smem ----
    {
        const float4* in4 = (const float4*)(inputs + (size_t)row0 * D_DIM);
        #pragma unroll
        for (int i = 0; i < 32; ++i) {
            int l   = i * 256 + t;           // 0..8191
            int row = l >> 6;
            int d4  = l & 63;
            float4 v = in4[row * 64 + d4];
            int d   = d4 * 4;
            int mt  = row >> 4, r16 = row & 15;
            int ks16 = d >> 4;               // k16 step 0..15
            int o    = d & 15;
            int reg  = ((o & 8) ? 2 : 0) + ((r16 >= 8) ? 1 : 0);
            int t0   = (o & 7) >> 1;         // thread-in-group for (v.x,v.y)
            uint32_t* p = fragA + ((mt * 16 + ks16) * 32 + (r16 & 7) * 4 + t0) * 4 + reg;
            p[0] = pack_bf2(v.x, v.y);
            p[4] = pack_bf2(v.z, v.w);       // t0+1 -> +4 u32
        }
    }

    // ---- Prefetch + stage B pair 0 (chunks 0,1; pure copy, conflict-free) ----
    uint4 pv[4];
    {
        const uint4* src = (const uint4*)d_eBfrag;
        uint4* dst = (uint4*)fragB;
        #pragma unroll
        for (int q = 0; q < 4; ++q) {
            pv[q] = src[q * 256 + t];
            dst[q * 256 + t] = pv[q];
        }
    }
    __syncthreads();

    float acc[16][4];
    #pragma unroll
    for (int nt = 0; nt < 16; ++nt)
        #pragma unroll
        for (int r = 0; r < 4; ++r) acc[nt][r] = 0.0f;

    float v1a = 3.4e38f, v2a = 3.4e38f; int i1a = 0;   // row wid*16 + lane/4
    float v1b = 3.4e38f, v2b = 3.4e38f; int i1b = 0;   // +8

    const uint32_t* fA = fragA + wid * 2048 + lane * 4;

    for (int p = 0; p < 32; ++p) {          // pair p covers chunks 2p, 2p+1
        // prefetch next pair (linear copy from preformatted gmem)
        if (p < 31) {
            const uint4* src = (const uint4*)(d_eBfrag + (size_t)(p + 1) * 4096);
            #pragma unroll
            for (int q = 0; q < 4; ++q) pv[q] = src[q * 256 + t];
        }

        // compute the 2 chunks of this pair
        #pragma unroll
        for (int h = 0; h < 2; ++h) {
            const int g = 2 * p + h;        // chunk id, g = kc*8 + dc
            const uint32_t* fB = fragB + (p & 1) * BSTRIDE + h * 2048 + lane * 2;
            #pragma unroll
            for (int ks = 0; ks < 2; ++ks) {
                int ks16 = (g & 7) * 2 + ks;
                uint4 a = *(const uint4*)(fA + ks16 * 128);
                #pragma unroll
                for (int nt = 0; nt < 16; ++nt) {
                    uint2 b = *(const uint2*)(fB + (ks * 16 + nt) * 64);
                    mma_bf16(acc[nt], a.x, a.y, a.z, a.w, b.x, b.y);
                }
            }
            // epilogue at end of each kc (g % 8 == 7, i.e. h==1 && p%4==3)
            if ((g & 7) == 7) {
                int kc = g >> 3;
                #pragma unroll
                for (int nt = 0; nt < 16; ++nt) {
                    int code = kc * 128 + nt * 8 + (lane & 3) * 2;
                    float c0 = sCn[code]     - 2.0f * acc[nt][0];
                    float c1 = sCn[code + 1] - 2.0f * acc[nt][1];
                    float c2 = sCn[code]     - 2.0f * acc[nt][2];
                    float c3 = sCn[code + 1] - 2.0f * acc[nt][3];
                    top2_upd(v1a, v2a, i1a, c0, code);
                    top2_upd(v1a, v2a, i1a, c1, code + 1);
                    top2_upd(v1b, v2b, i1b, c2, code);
                    top2_upd(v1b, v2b, i1b, c3, code + 1);
                    acc[nt][0] = acc[nt][1] = acc[nt][2] = acc[nt][3] = 0.0f;
                }
            }
        }

        // store next pair into the other buffer
        if (p < 31) {
            uint4* dst = (uint4*)(fragB + ((p + 1) & 1) * BSTRIDE);
            #pragma unroll
            for (int q = 0; q < 4; ++q) dst[q * 256 + t] = pv[q];
        }
        __syncthreads();
    }

    // ---- merge top-2 across the 4 lanes sharing each row ----
    #pragma unroll
    for (int off = 1; off < 4; off <<= 1) {
        float w1 = __shfl_down_sync(0xffffffffu, v1a, off, 4);
        int   wi = __shfl_down_sync(0xffffffffu, i1a, off, 4);
        float w2 = __shfl_down_sync(0xffffffffu, v2a, off, 4);
        if (w1 < v1a || (w1 == v1a && wi < i1a)) {
            v2a = fminf(v1a, w2); v1a = w1; i1a = wi;
        } else v2a = fminf(v2a, w1);
        w1 = __shfl_down_sync(0xffffffffu, v1b, off, 4);
        wi = __shfl_down_sync(0xffffffffu, i1b, off, 4);
        w2 = __shfl_down_sync(0xffffffffu, v2b, off, 4);
        if (w1 < v1b || (w1 == v1b && wi < i1b)) {
            v2b = fminf(v1b, w2); v1b = w1; i1b = wi;
        } else v2b = fminf(v2b, w1);
    }

    const size_t ND = (size_t)N_ROWS * D_DIM;
    if ((lane & 3) == 0) {
        int rA = wid * 16 + (lane >> 2);
        int rB = rA + 8;
        sIdx[rA] = i1a;
        sIdx[rB] = i1b;
        if (v2a - v1a < FLAG_THRESH) {
            int pos = atomicAdd(&d_nflag, 1);
            d_flaglist[pos] = row0 + rA;
        }
        if (v2b - v1b < FLAG_THRESH) {
            int pos = atomicAdd(&d_nflag, 1);
            d_flaglist[pos] = row0 + rB;
        }
        atomicAdd(&d_counts[i1a], 1u);
        atomicAdd(&d_counts[i1b], 1u);
        out[ND + 2 + (size_t)(row0 + rA)] = (float)i1a;
        out[ND + 2 + (size_t)(row0 + rB)] = (float)i1b;
    }
    __syncthreads();

    // ---- quantize (= q exactly) + loss partials ----
    float lsum = 0.0f;
    const float4* inp4 = (const float4*)(inputs + (size_t)row0 * D_DIM);
    float4*       out4 = (float4*)(out + (size_t)row0 * D_DIM);
    const float4* eT4  = (const float4*)d_embedT;
    #pragma unroll 4
    for (int it = 0; it < 32; ++it) {
        int l  = it * 256 + t;
        int r  = l >> 6;
        int d4 = l & 63;
        float4 x = inp4[r * 64 + d4];
        int    k = sIdx[r];
        float4 q = eT4[(size_t)k * 64 + d4];
        float dx = q.x - x.x, dy = q.y - x.y, dz = q.z - x.z, dw = q.w - x.w;
        lsum += dx * dx + dy * dy + dz * dz + dw * dw;
        out4[r * 64 + d4] = q;
    }
    #pragma unroll
    for (int off = 16; off; off >>= 1)
        lsum += __shfl_down_sync(0xffffffffu, lsum, off);
    if ((t & 31) == 0) sRed[t >> 5] = lsum;
    __syncthreads();
    if (t == 0) {
        float s = 0.0f;
        #pragma unroll
        for (int w = 0; w < 8; ++w) s += sRed[w];
        d_loss_partial[blockIdx.x] = s;
    }
}

// ---------------------------------------------------------------------------
// Rescue: re-decide flagged rows with reference-emulated fp32 arithmetic
// ---------------------------------------------------------------------------
__global__ void __launch_bounds__(256)
vq_fix(const float* __restrict__ inputs, float* __restrict__ out) {
    __shared__ float sx[RESCUE_RPB][D_DIM];
    __shared__ float sdist[RESCUE_RPB][K_CODES];
    __shared__ float ssx2[RESCUE_RPB];
    __shared__ int   srow[RESCUE_RPB];
    __shared__ int   sbest[RESCUE_RPB];
    const int t = threadIdx.x;
    const size_t ND = (size_t)N_ROWS * D_DIM;

    const int nf = d_nflag;
    for (int base = blockIdx.x * RESCUE_RPB; base < nf;
         base += gridDim.x * RESCUE_RPB) {
        const int cnt = min(RESCUE_RPB, nf - base);
        __syncthreads();
        if (t < cnt) srow[t] = d_flaglist[base + t];
        __syncthreads();
        for (int r = 0; r < cnt; ++r)
            sx[r][t] = inputs[(size_t)srow[r] * D_DIM + t];
        __syncthreads();
        if (t < cnt) {
            float s = 0.0f;
            for (int d = 0; d < D_DIM; ++d)
                s = __fadd_rn(s, __fmul_rn(sx[t][d], sx[t][d]));
            ssx2[t] = s;
        }
        __syncthreads();

        #pragma unroll
        for (int c = 0; c < 4; ++c) {
            const int k = c * 256 + t;
            const float* e = d_embedT + (size_t)k * D_DIM;
            float acc[RESCUE_RPB];
            #pragma unroll
            for (int r = 0; r < RESCUE_RPB; ++r) acc[r] = 0.0f;
            for (int d = 0; d < D_DIM; ++d) {
                float ev = e[d];
                #pragma unroll
                for (int r = 0; r < RESCUE_RPB; ++r)
                    acc[r] = __fmaf_rn(sx[r][d], ev, acc[r]);
            }
            #pragma unroll
            for (int r = 0; r < RESCUE_RPB; ++r) {
                float twod = __fadd_rn(acc[r], acc[r]);
                float t1   = __fsub_rn(ssx2[r], twod);
                sdist[r][k] = __fadd_rn(t1, d_cnorm[k]);
            }
        }
        __syncthreads();

        if (t < cnt) {
            float best = 3.4e38f; int bk = 0;
            for (int k = 0; k < K_CODES; ++k) {
                float v = sdist[t][k];
                if (v < best) { best = v; bk = k; }
            }
            sbest[t] = bk;
            int oldk = (int)out[ND + 2 + (size_t)srow[t]];
            if (oldk != bk) {
                atomicAdd(&d_counts[bk], 1u);
                atomicAdd(&d_counts[oldk], 0xFFFFFFFFu);
                out[ND + 2 + (size_t)srow[t]] = (float)bk;
            }
        }
        __syncthreads();
        for (int r = 0; r < cnt; ++r)
            out[(size_t)srow[r] * D_DIM + t] =
                d_embedT[(size_t)sbest[r] * D_DIM + t];
    }
}

// ---------------------------------------------------------------------------
// Finalize: loss mean + perplexity
// ---------------------------------------------------------------------------
__global__ void vq_finalize(float* __restrict__ out) {
    __shared__ float sl[1024];
    __shared__ float se[1024];
    int t = threadIdx.x;
    sl[t] = d_loss_partial[t];
    float avg = (float)d_counts[t] * (1.0f / (float)N_ROWS);
    se[t] = avg * logf(avg + 1e-10f);
    __syncthreads();
    for (int s = 512; s; s >>= 1) {
        if (t < s) { sl[t] += sl[t + s]; se[t] += se[t + s]; }
        __syncthreads();
    }
    if (t == 0) {
        const size_t ND = (size_t)N_ROWS * D_DIM;
        out[ND]     = sl[0] / ((float)N_ROWS * (float)D_DIM);
        out[ND + 1] = expf(-se[0]);
    }
}

// ---------------------------------------------------------------------------
extern "C" void kernel_launch(void* const* d_in, const int* in_sizes, int n_in,
                              void* d_out, int out_size) {
    const float* inputs = (const float*)d_in[0];  // [131072, 256]
    const float* embed  = (const float*)d_in[1];  // [256, 1024]
    float* out = (float*)d_out;

    cudaFuncSetAttribute(vq_main_mma,
                         cudaFuncAttributeMaxDynamicSharedMemorySize,
                         SMEM_TOTAL);

    vq_prep<<<8, 128>>>(embed);
    vq_prep_frag<<<64, 256>>>(embed);
    vq_main_mma<<<N_ROWS / 128, 256, SMEM_TOTAL>>>(inputs, out);
    vq_fix<<<256, 256>>>(inputs, out);
    vq_finalize<<<1, 1024>>>(out);
}